// round 16
// baseline (speedup 1.0000x reference)
#include <cuda_runtime.h>
#include <cstdint>

#define NDOC  128
#define NIN   625
#define NLEAF 4096
#define CSC   16       // colsum row-chunks
#define GEMM_KB 12     // main gemm K-split
#define GKB     12     // G gemm K-split (3 tile-pairs x 12 = 36 blocks)
#define GSLOT   20     // inner Gram K-slots (slot0: features 0..31; rest cover 32..624)

// ---------------- scratch (device globals; no allocation) ----------------
__device__ __align__(16) float g_cs[CSC][NLEAF];
__device__ __align__(16) float g_Wp[GEMM_KB][NIN * NDOC];       // split-K partials of W
__device__ __align__(16) float g_z[NIN * NDOC];                 // centered z, node-major [p][d]
__device__ __align__(16) float g_outp[GSLOT][NDOC * NDOC];      // inner Gram partials
__device__ __align__(16) float g_Gp[GKB][NDOC * NDOC];          // mass@mass.T partials

// -------- 1. partial column sums of exp(param) --------
__global__ __launch_bounds__(256) void k_colsum(const float* __restrict__ param) {
    int col = blockIdx.x * 256 + threadIdx.x;
    int rc  = blockIdx.y;
    int r0 = rc * 40;
    int r1 = min(r0 + 40, NIN);
    float s = 0.f;
    for (int r = r0; r < r1; r++)
        s += __expf(param[r * NLEAF + col]);
    g_cs[rc][col] = s;
}

// -------- 2. fused big wave: W-gemm (blocks 0..239) + G-gemm (blocks 240..275) --------
__constant__ int c_gbi[3] = {0, 0, 1};
__constant__ int c_gbj[3] = {0, 1, 1};

__global__ __launch_bounds__(256, 2) void k_big(const float* __restrict__ mass,
                                                const float* __restrict__ param) {
    __shared__ __align__(16) float sbuf[5728];
    int bx = blockIdx.x;
    int t = threadIdx.x;

    if (bx < 240) {
        // ===== W = (mass * rs) @ exp(param).T, fp32 FFMA 4x4 micro-tile =====
        float* sA  = sbuf;               // [32][132]
        float* sB  = sbuf + 4224;        // [32][36]
        float* srs = sbuf + 4224 + 1152; // up to 352 cols
        int j0 = (bx % 20) * 32;
        int kb = bx / 20;
        int t0 = kb * 10 + min(kb, 8);
        int nt = 10 + (kb < 8 ? 1 : 0);
        int l0 = t0 * 32;
        int ncol = nt * 32;
        int lane = t & 31;
        int jg = t >> 5;

        for (int c = t; c < ncol; c += 256) {
            float s = 0.f;
#pragma unroll
            for (int y = 0; y < CSC; y++) s += g_cs[y][l0 + c];
            srs[c] = 1.0f / s;
        }
        __syncthreads();

        float acc[4][4];
#pragma unroll
        for (int r = 0; r < 4; r++)
#pragma unroll
            for (int c = 0; c < 4; c++) acc[r][c] = 0.f;

        for (int kt = 0; kt < nt; kt++) {
            int lb = (t0 + kt) * 32;
#pragma unroll
            for (int i = 0; i < 16; i++) {
                int idx = t + i * 256;
                int kk = idx & 31, d = idx >> 5;
                sA[kk * 132 + d] = mass[d * NLEAF + lb + kk] * srs[kt * 32 + kk];
            }
#pragma unroll
            for (int i = 0; i < 4; i++) {
                int idx = t + i * 256;
                int kk = idx & 31, jj = idx >> 5;
                int j = j0 + jj;
                sB[kk * 36 + jj] = (j < NIN) ? __expf(param[j * NLEAF + lb + kk]) : 0.f;
            }
            __syncthreads();
#pragma unroll
            for (int k = 0; k < 32; k++) {
                float4 a = *(const float4*)&sA[k * 132 + 4 * lane];
                float4 b = *(const float4*)&sB[k * 36 + jg * 4];
                acc[0][0] += a.x * b.x; acc[0][1] += a.x * b.y; acc[0][2] += a.x * b.z; acc[0][3] += a.x * b.w;
                acc[1][0] += a.y * b.x; acc[1][1] += a.y * b.y; acc[1][2] += a.y * b.z; acc[1][3] += a.y * b.w;
                acc[2][0] += a.z * b.x; acc[2][1] += a.z * b.y; acc[2][2] += a.z * b.z; acc[2][3] += a.z * b.w;
                acc[3][0] += a.w * b.x; acc[3][1] += a.w * b.y; acc[3][2] += a.w * b.z; acc[3][3] += a.w * b.w;
            }
            __syncthreads();
        }
#pragma unroll
        for (int c = 0; c < 4; c++) {
            int j = j0 + jg * 4 + c;
            if (j < NIN)
                *(float4*)&g_Wp[kb][j * NDOC + 4 * lane] =
                    make_float4(acc[0][c], acc[1][c], acc[2][c], acc[3][c]);
        }
    } else {
        // ===== G = mass @ mass.T, 64x64 tiles, fp32 exact =====
        float* sI = sbuf;               // [32][68]
        float* sJ = sbuf + 2176;        // [32][68]
        int g  = bx - 240;
        int gt = g % 3;
        int kb = g / 3;
        int i0 = c_gbi[gt] * 64, j0 = c_gbj[gt] * 64;
        bool offdiag = (i0 != j0);
        int t0 = kb * 10 + min(kb, 8);
        int nt = 10 + (kb < 8 ? 1 : 0);
        int iq = t >> 4, jq = t & 15;

        float acc[4][4];
#pragma unroll
        for (int r = 0; r < 4; r++)
#pragma unroll
            for (int c = 0; c < 4; c++) acc[r][c] = 0.f;

        for (int kt = 0; kt < nt; kt++) {
            int lb = (t0 + kt) * 32;
#pragma unroll
            for (int i = 0; i < 8; i++) {
                int idx = t + i * 256;
                int kk = idx & 31, ii = idx >> 5;
                sI[kk * 68 + ii] = mass[(i0 + ii) * NLEAF + lb + kk];
                sJ[kk * 68 + ii] = mass[(j0 + ii) * NLEAF + lb + kk];
            }
            __syncthreads();
#pragma unroll
            for (int k = 0; k < 32; k++) {
                float4 a = *(const float4*)&sI[k * 68 + iq * 4];
                float4 b = *(const float4*)&sJ[k * 68 + jq * 4];
                acc[0][0] += a.x * b.x; acc[0][1] += a.x * b.y; acc[0][2] += a.x * b.z; acc[0][3] += a.x * b.w;
                acc[1][0] += a.y * b.x; acc[1][1] += a.y * b.y; acc[1][2] += a.y * b.z; acc[1][3] += a.y * b.w;
                acc[2][0] += a.z * b.x; acc[2][1] += a.z * b.y; acc[2][2] += a.z * b.z; acc[2][3] += a.z * b.w;
                acc[3][0] += a.w * b.x; acc[3][1] += a.w * b.y; acc[3][2] += a.w * b.z; acc[3][3] += a.w * b.w;
            }
            __syncthreads();
        }
        float* op = g_Gp[kb];
#pragma unroll
        for (int r = 0; r < 4; r++) {
            int i = i0 + iq * 4 + r;
            *(float4*)&op[i * NDOC + j0 + jq * 4] =
                make_float4(acc[r][0], acc[r][1], acc[r][2], acc[r][3]);
        }
        if (offdiag) {
#pragma unroll
            for (int r = 0; r < 4; r++)
#pragma unroll
                for (int c = 0; c < 4; c++)
                    op[(j0 + jq * 4 + c) * NDOC + i0 + iq * 4 + r] = acc[r][c];
        }
    }
}

// -------- 3. combine split-K partials + tree phase 1 + PER-ROW CENTERING --------
// g_z gets subtree sums (nodes 31..624) / raw W (0..30), each row centered over
// docs. Pairwise z-differences are invariant to per-feature shifts; centering
// makes the inner Gram cancellation O(1) instead of O(1e8).
__global__ __launch_bounds__(256) void k_combine() {
    __shared__ float red[8];                 // 2 rows x 4 warps
    int idx = blockIdx.x * 256 + threadIdx.x;
    int t = threadIdx.x;
    bool ok = idx < NIN * NDOC;
    float s = 0.f;
    if (ok) {
        int n = idx >> 7, d = idx & 127;
#pragma unroll
        for (int kb = 0; kb < GEMM_KB; kb++) s += g_Wp[kb][idx];
        if (n >= 31 && n <= 124) {
            int c0 = 5 * n + 1;
            int c1 = min(c0 + 5, NIN);
            for (int c = c0; c < c1; c++) {
                int cidx = c * NDOC + d;
#pragma unroll
                for (int kb = 0; kb < GEMM_KB; kb++) s += g_Wp[kb][cidx];
            }
        }
    }
    // row mean: block = 2 rows of 128 threads (4 warps each)
    float v = ok ? s : 0.f;
#pragma unroll
    for (int o = 16; o > 0; o >>= 1) v += __shfl_xor_sync(0xffffffffu, v, o);
    if ((t & 31) == 0) red[t >> 5] = v;
    __syncthreads();
    int base = (t >> 7) * 4;
    float mean = (red[base] + red[base + 1] + red[base + 2] + red[base + 3]) * (1.0f / 128.0f);
    if (ok) g_z[idx] = s - mean;
}

// -------- 4. inner Gram: Gz = Z^T Z over centered z (64x64 tiles, 20 K-slots) --------
// Slot 0 blocks build subtree-complete rows 0..31 directly into their k-tile
// (sI/sJ) via the 3-phase tree prologue; other slots load g_z straight.
__global__ __launch_bounds__(256) void k_gram() {
    __shared__ __align__(16) float sI[32 * 68];
    __shared__ __align__(16) float sJ[32 * 68];
    int gt = blockIdx.x;            // 0..2 tile pair
    int s  = blockIdx.y;            // 0..19 K-slot
    int i0 = c_gbi[gt] * 64, j0 = c_gbj[gt] * 64;
    bool offdiag = (i0 != j0);
    int t = threadIdx.x;
    int iq = t >> 4, jq = t & 15;

    if (s == 0) {
        // phase A: p=6..30 subtree sums (children 31..155 complete) + p=31 copy
        for (int it = t; it < 26 * 128; it += 256) {
            int p = 6 + (it >> 7), dd = it & 127;
            int doc = (dd < 64) ? i0 + dd : j0 + (dd - 64);
            float sv;
            if (p < 31) {
                sv = g_z[p * NDOC + doc];
                int c0 = 5 * p + 1;
#pragma unroll
                for (int c = 0; c < 5; c++) sv += g_z[(c0 + c) * NDOC + doc];
            } else {
                sv = g_z[31 * NDOC + doc];
            }
            float* dst = (dd < 64) ? sI : sJ;
            dst[p * 68 + (dd & 63)] = sv;
        }
        __syncthreads();
        // phase B: p=1..5 (children 6..30 now in sI/sJ)
        for (int it = t; it < 5 * 128; it += 256) {
            int p = 1 + (it >> 7), dd = it & 127;
            int doc = (dd < 64) ? i0 + dd : j0 + (dd - 64);
            float* buf = (dd < 64) ? sI : sJ;
            float sv = g_z[p * NDOC + doc];
            int c0 = 5 * p + 1;
#pragma unroll
            for (int c = 0; c < 5; c++) sv += buf[(c0 + c) * 68 + (dd & 63)];
            buf[p * 68 + (dd & 63)] = sv;
        }
        __syncthreads();
        // phase C: root (children 1..5 in buffers)
        if (t < 128) {
            int dd = t;
            int doc = (dd < 64) ? i0 + dd : j0 + (dd - 64);
            float* buf = (dd < 64) ? sI : sJ;
            float sv = g_z[doc];
#pragma unroll
            for (int c = 1; c <= 5; c++) sv += buf[c * 68 + (dd & 63)];
            buf[(dd & 63)] = sv;
        }
        __syncthreads();
    } else {
        // features: 4 slots of 32 (s=1..4), 15 slots of 31 (s=5..19); covers 32..624
        int ks = 32 + (s - 1) * 31 + min(s - 1, 4);
        int ke = 32 + s * 31 + min(s, 4);
        for (int it = t; it < 32 * 64; it += 256) {
            int kk = it >> 6, ii = it & 63;
            int kg = ks + kk;
            sI[kk * 68 + ii] = (kg < ke) ? g_z[kg * NDOC + i0 + ii] : 0.f;
            sJ[kk * 68 + ii] = (kg < ke) ? g_z[kg * NDOC + j0 + ii] : 0.f;
        }
        __syncthreads();
    }

    float acc[4][4];
#pragma unroll
    for (int r = 0; r < 4; r++)
#pragma unroll
        for (int c = 0; c < 4; c++) acc[r][c] = 0.f;
#pragma unroll
    for (int k = 0; k < 32; k++) {
        float4 a = *(const float4*)&sI[k * 68 + iq * 4];
        float4 b = *(const float4*)&sJ[k * 68 + jq * 4];
        acc[0][0] += a.x * b.x; acc[0][1] += a.x * b.y; acc[0][2] += a.x * b.z; acc[0][3] += a.x * b.w;
        acc[1][0] += a.y * b.x; acc[1][1] += a.y * b.y; acc[1][2] += a.y * b.z; acc[1][3] += a.y * b.w;
        acc[2][0] += a.z * b.x; acc[2][1] += a.z * b.y; acc[2][2] += a.z * b.z; acc[2][3] += a.z * b.w;
        acc[3][0] += a.w * b.x; acc[3][1] += a.w * b.y; acc[3][2] += a.w * b.z; acc[3][3] += a.w * b.w;
    }
    float* op = g_outp[s];
#pragma unroll
    for (int r = 0; r < 4; r++) {
        int i = i0 + iq * 4 + r;
        *(float4*)&op[i * NDOC + j0 + jq * 4] =
            make_float4(acc[r][0], acc[r][1], acc[r][2], acc[r][3]);
    }
    if (offdiag) {
#pragma unroll
        for (int r = 0; r < 4; r++)
#pragma unroll
            for (int c = 0; c < 4; c++)
                op[(j0 + jq * 4 + c) * NDOC + i0 + iq * 4 + r] = acc[r][c];
    }
}

// -------- 5. final reduce: both distances via norm identity; exact 0 diagonal --------
__global__ __launch_bounds__(256) void k_reduce(float* __restrict__ out) {
    int idx = blockIdx.x * 256 + threadIdx.x;   // 64*256 = 16384 exact
    int i = idx >> 7, j = idx & 127;
    int di = i * (NDOC + 1), dj = j * (NDOC + 1);
    float gg = 0.f, ni = 0.f, nj = 0.f;
#pragma unroll
    for (int kb = 0; kb < GKB; kb++) {
        gg += g_Gp[kb][idx];
        ni += g_Gp[kb][di];
        nj += g_Gp[kb][dj];
    }
    float s = ni + nj - 2.0f * gg;              // d_leaf
    float gz = 0.f, mi = 0.f, mj = 0.f;
#pragma unroll
    for (int ts = 0; ts < GSLOT; ts++) {
        gz += g_outp[ts][idx];
        mi += g_outp[ts][di];
        mj += g_outp[ts][dj];
    }
    s += mi + mj - 2.0f * gz;                   // d_inner (centered Gram)
    out[idx] = (i == j) ? 0.f : s;
}

// ---------------- launch ----------------
extern "C" void kernel_launch(void* const* d_in, const int* in_sizes, int n_in,
                              void* d_out, int out_size) {
    const float* mass  = (const float*)d_in[0];   // (128, 4096)
    const float* param = (const float*)d_in[1];   // (625, 4096)
    if (n_in >= 2 && in_sizes[0] == NIN * NLEAF && in_sizes[1] == NDOC * NLEAF) {
        param = (const float*)d_in[0];
        mass  = (const float*)d_in[1];
    }
    float* out = (float*)d_out;

    k_colsum<<<dim3(16, CSC), 256>>>(param);
    k_big<<<240 + 3 * GKB, 256>>>(mass, param);
    k_combine<<<(NIN * NDOC + 255) / 256, 256>>>();
    k_gram<<<dim3(3, GSLOT), 256>>>();
    k_reduce<<<64, 256>>>(out);
}